// round 16
// baseline (speedup 1.0000x reference)
#include <cuda_runtime.h>
#include <cuda_bf16.h>
#include <math.h>
#include <stdint.h>

#define BB   8
#define SS   1024
#define DD   1024
#define HH   16
#define DKK  64
#define CFF  256
#define MT   (BB*SS)
#define OUT_ELEMS  (MT*DD)
#define SCALE_F 512.0f

__device__ float d_qbuf[MT*DD];
__device__ float d_kbuf[MT*DD];
__device__ float d_vbuf[MT*DD];
__device__ float d_caddbuf[3*BB*DD];
__device__ __nv_bfloat16 d_aplanes[(size_t)3*MT*DD];
__device__ __nv_bfloat16 d_kplanes[(size_t)3*MT*DD];
__device__ __nv_bfloat16 d_wplanes[(size_t)4*3*DD*DD];
__device__ __nv_bfloat16 d_vtpl[(size_t)2*BB*HH*DKK*SS];

#define APL ((size_t)MT*DD)
#define WPL ((size_t)DD*DD)
#define VTPL ((size_t)BB*HH*DKK*SS)

// ---------------- helpers -------------------------------------------------------
__device__ __forceinline__ uint32_t smem_u32(const void* p){
    uint32_t a; asm("{.reg .u64 t; cvta.to.shared.u64 t, %1; cvt.u32.u64 %0, t;}":"=r"(a):"l"(p)); return a;
}
__device__ __forceinline__ void ldsm_x4(uint32_t* r, uint32_t addr){
    asm volatile("ldmatrix.sync.aligned.m8n8.x4.shared.b16 {%0,%1,%2,%3}, [%4];"
        : "=r"(r[0]),"=r"(r[1]),"=r"(r[2]),"=r"(r[3]) : "r"(addr));
}
__device__ __forceinline__ void ldsm_x2(uint32_t* r, uint32_t addr){
    asm volatile("ldmatrix.sync.aligned.m8n8.x2.shared.b16 {%0,%1}, [%2];"
        : "=r"(r[0]),"=r"(r[1]) : "r"(addr));
}
__device__ __forceinline__ void mma16816(float* d, const uint32_t* a, const uint32_t* b){
    asm volatile("mma.sync.aligned.m16n8k16.row.col.f32.bf16.bf16.f32 "
        "{%0,%1,%2,%3}, {%4,%5,%6,%7}, {%8,%9}, {%0,%1,%2,%3};"
        : "+f"(d[0]),"+f"(d[1]),"+f"(d[2]),"+f"(d[3])
        : "r"(a[0]),"r"(a[1]),"r"(a[2]),"r"(a[3]), "r"(b[0]),"r"(b[1]));
}
__device__ __forceinline__ void split3(float a, __nv_bfloat16& h0, __nv_bfloat16& h1, __nv_bfloat16& h2){
    h0 = __float2bfloat16(a);
    float r = a - __bfloat162float(h0);
    h1 = __float2bfloat16(r);
    h2 = __float2bfloat16(r - __bfloat162float(h1));
}

__global__ void splitA_kernel(const float* __restrict__ X, __nv_bfloat16* __restrict__ P){
    size_t base = (size_t)blockIdx.x*DD;
    int t = threadIdx.x;
    float4 v = ((const float4*)(X+base))[t];
    __nv_bfloat16 a[3], b[3], c[3], d[3];
    split3(v.x,a[0],a[1],a[2]); split3(v.y,b[0],b[1],b[2]);
    split3(v.z,c[0],c[1],c[2]); split3(v.w,d[0],d[1],d[2]);
#pragma unroll
    for (int p=0;p<3;p++){
        __nv_bfloat162* dst = (__nv_bfloat162*)(P + p*APL + base + t*4);
        dst[0] = __nv_bfloat162(a[p], b[p]);
        dst[1] = __nv_bfloat162(c[p], d[p]);
    }
}

__global__ void splitWT_kernel(const float* __restrict__ W0, const float* __restrict__ W1,
                               const float* __restrict__ W2, const float* __restrict__ W3,
                               __nv_bfloat16* __restrict__ Pall){
    __shared__ float tile[32][33];
    int z = blockIdx.z;
    const float* W = (z==0)?W0:((z==1)?W1:((z==2)?W2:W3));
    __nv_bfloat16* P = Pall + (size_t)z*3*WPL;
    int n0 = blockIdx.x*32, k0 = blockIdx.y*32;
    int tx = threadIdx.x&31, ty = threadIdx.x>>5;
#pragma unroll
    for (int i=0;i<32;i+=8)
        tile[ty+i][tx] = W[(size_t)(k0+ty+i)*DD + n0+tx];
    __syncthreads();
#pragma unroll
    for (int i=0;i<32;i+=8){
        float a = tile[tx][ty+i];
        __nv_bfloat16 h0,h1,h2; split3(a,h0,h1,h2);
        size_t o = (size_t)(n0+ty+i)*DD + k0+tx;
        P[0*WPL+o]=h0; P[1*WPL+o]=h1; P[2*WPL+o]=h2;
    }
}

__global__ void vtrans_kernel(const float* __restrict__ vb, __nv_bfloat16* __restrict__ vt){
    __shared__ float tile[32][33];
    int dt = blockIdx.x, s0 = blockIdx.y*32, bh = blockIdx.z;
    int b = bh>>4, h = bh&15, d0 = dt*32;
    int t = threadIdx.x;
    int sr = t>>3, dc = (t&7)*4;
    float4 v = *(const float4*)(vb + (size_t)(b*SS + s0+sr)*DD + h*DKK + d0 + dc);
    tile[sr][dc]=v.x; tile[sr][dc+1]=v.y; tile[sr][dc+2]=v.z; tile[sr][dc+3]=v.w;
    __syncthreads();
    int dr = t>>3, sc = (t&7)*4;
    __nv_bfloat16 o0[4], o1[4];
#pragma unroll
    for (int j=0;j<4;j++){
        float val = tile[sc+j][dr];
        o0[j] = __float2bfloat16(val);
        o1[j] = __float2bfloat16(val - __bfloat162float(o0[j]));
    }
    size_t dst = (size_t)bh*DKK*SS + (size_t)(d0+dr)*SS + s0+sc;
    *(uint2*)(vt + dst)        = *(uint2*)o0;
    *(uint2*)(vt + VTPL + dst) = *(uint2*)o1;
}

// ---------- split-bf16 mma.sync GEMM (champion core, z-merged q/k/v) ----------------
#define STRB  144
#define PLSZ  (128*STRB)
#define GEMM_SMEM_MAX (6*PLSZ)

__device__ __forceinline__ void gemm_body(
    const __nv_bfloat16* __restrict__ Apl, const __nv_bfloat16* __restrict__ Bpl,
    const float* __restrict__ bias, float* __restrict__ C, int pc, char* smc)
{
    int t=threadIdx.x, lane=t&31, wid=t>>5;
    int m0=blockIdx.y*128, n0=blockIdx.x*128;
    int wm=(wid>>2)*64, wn=(wid&3)*32;
    uint32_t sb = smem_u32(smc);

    float acc[16][4];
#pragma unroll
    for (int i=0;i<16;i++)
#pragma unroll
        for (int j=0;j<4;j++) acc[i][j]=0.f;

    for (int ch=0; ch<16; ch++){
        int kc = ch*64;
        for (int p=0;p<pc;p++){
            const __nv_bfloat16* As  = Apl + (size_t)p*APL + (size_t)m0*DD + kc;
            const __nv_bfloat16* Bs2 = Bpl + (size_t)p*WPL + (size_t)n0*DD + kc;
            char* da = smc + p*PLSZ;
            char* db = smc + (pc+p)*PLSZ;
#pragma unroll
            for (int i=0;i<8;i++){
                int idx=t+i*256, r=idx>>4, c4=(idx&15)*4;
                uint2 va = *(const uint2*)(As  + (size_t)r*DD + c4);
                *(uint2*)(da + r*STRB + c4*2) = va;
                uint2 vb = *(const uint2*)(Bs2 + (size_t)r*DD + c4);
                *(uint2*)(db + r*STRB + c4*2) = vb;
            }
        }
        __syncthreads();
#pragma unroll
        for (int ks=0;ks<4;ks++){
            for (int ap=0; ap<pc; ap++){
                uint32_t Abase = sb + ap*PLSZ;
                uint32_t ar[4][4];
#pragma unroll
                for (int mt=0;mt<4;mt++)
                    ldsm_x4(ar[mt], Abase + (wm+mt*16+(lane&15))*STRB + ks*32 + (lane>>4)*16);
                for (int bp=0; bp<pc-ap; bp++){
                    uint32_t Bbase = sb + (pc+bp)*PLSZ;
                    uint32_t br[4][2];
#pragma unroll
                    for (int nt=0;nt<4;nt++)
                        ldsm_x2(br[nt], Bbase + (wn+nt*8+(lane&7))*STRB + ks*32 + ((lane>>3)&1)*16);
#pragma unroll
                    for (int mt=0;mt<4;mt++)
#pragma unroll
                        for (int nt=0;nt<4;nt++)
                            mma16816(acc[mt*4+nt], ar[mt], br[nt]);
                }
            }
        }
        __syncthreads();
    }

    int tr = lane>>2, tc = (lane&3)*2;
#pragma unroll
    for (int mt=0;mt<4;mt++)
#pragma unroll
        for (int nt=0;nt<4;nt++){
            int m = m0+wm+mt*16+tr, n = n0+wn+nt*8+tc;
            float b0 = bias[n], b1 = bias[n+1];
            float* c0 = C + (size_t)m*DD + n;
            float* c1 = C + (size_t)(m+8)*DD + n;
            c0[0]=acc[mt*4+nt][0]+b0; c0[1]=acc[mt*4+nt][1]+b1;
            c1[0]=acc[mt*4+nt][2]+b0; c1[1]=acc[mt*4+nt][3]+b1;
        }
}

__global__ void __launch_bounds__(256,2) gemm_mma_qkv(
    const __nv_bfloat16* __restrict__ Apl, const __nv_bfloat16* __restrict__ Wall,
    const float* __restrict__ bq, const float* __restrict__ bk, const float* __restrict__ bv,
    float* __restrict__ qb, float* __restrict__ kb, float* __restrict__ vb)
{
    extern __shared__ char smc[];
    int z = blockIdx.z;
    const __nv_bfloat16* Bpl = Wall + (size_t)z*3*WPL;
    const float* bias = (z==0)?bq:((z==1)?bk:bv);
    float* C = (z==0)?qb:((z==1)?kb:vb);
    int pc = (z==2)?2:3;
    gemm_body(Apl, Bpl, bias, C, pc, smc);
}

__global__ void __launch_bounds__(256,2) gemm_mma(
    const __nv_bfloat16* __restrict__ Apl, const __nv_bfloat16* __restrict__ Bpl,
    const float* __restrict__ bias, float* __restrict__ C, int npairs)
{
    extern __shared__ char smc[];
    gemm_body(Apl, Bpl, bias, C, (npairs==6)?3:2, smc);
}

// ---------- qk mma (champion, frozen) ------------------------------------------------
#define QKPL 16384
__global__ void __launch_bounds__(256,2) qk_mma(
    const __nv_bfloat16* __restrict__ qpl, const __nv_bfloat16* __restrict__ kpl,
    float* __restrict__ attn)
{
    extern __shared__ char smc[];
    int t=threadIdx.x, lane=t&31, wid=t>>5;
    int bh = blockIdx.z, b = bh>>4, h = bh&15;
    int m0 = blockIdx.y*128, n0 = blockIdx.x*128;
    int wm=(wid>>2)*64, wn=(wid&3)*32;
    uint32_t sb = smem_u32(smc);

#pragma unroll
    for (int p=0;p<3;p++){
        const __nv_bfloat16* qs = qpl + (size_t)p*APL + (size_t)(b*SS+m0)*DD + h*DKK;
        const __nv_bfloat16* ks2= kpl + (size_t)p*APL + (size_t)(b*SS+n0)*DD + h*DKK;
        char* da = smc + p*QKPL;
        char* db = smc + (3+p)*QKPL;
#pragma unroll
        for (int i=0;i<8;i++){
            int u = t + i*256;
            int r = u>>4, sub = u&15;
            uint32_t off = (uint32_t)(r*128 + (((sub>>1) ^ (r&7))<<4) + (sub&1)*8);
            *(uint2*)(da + off) = *(const uint2*)(qs + (size_t)r*DD + sub*4);
            *(uint2*)(db + off) = *(const uint2*)(ks2 + (size_t)r*DD + sub*4);
        }
    }
    __syncthreads();

    float acc[16][4];
#pragma unroll
    for (int i=0;i<16;i++)
#pragma unroll
        for (int j=0;j<4;j++) acc[i][j]=0.f;

#pragma unroll
    for (int ks=0;ks<4;ks++){
        for (int ap=0; ap<3; ap++){
            uint32_t Abase = sb + ap*QKPL;
            uint32_t ar[4][4];
#pragma unroll
            for (int mt=0;mt<4;mt++){
                int r = wm+mt*16+(lane&15);
                int u16 = ks*2 + (lane>>4);
                ldsm_x4(ar[mt], Abase + r*128 + ((u16 ^ (r&7))<<4));
            }
            for (int bp=0; bp<3-ap; bp++){
                uint32_t Bbase = sb + (3+bp)*QKPL;
                uint32_t br[4][2];
#pragma unroll
                for (int nt=0;nt<4;nt++){
                    int r = wn+nt*8+(lane&7);
                    int u16 = ks*2 + ((lane>>3)&1);
                    ldsm_x2(br[nt], Bbase + r*128 + ((u16 ^ (r&7))<<4));
                }
#pragma unroll
                for (int mt=0;mt<4;mt++)
#pragma unroll
                    for (int nt=0;nt<4;nt++)
                        mma16816(acc[mt*4+nt], ar[mt], br[nt]);
            }
        }
    }

    float* obase = attn + (size_t)bh*SS*SS;
    int tr = lane>>2, tc = (lane&3)*2;
#pragma unroll
    for (int mt=0;mt<4;mt++)
#pragma unroll
        for (int nt=0;nt<4;nt++){
            int m = m0+wm+mt*16+tr, n = n0+wn+nt*8+tc;
            float* c0 = obase + (size_t)m*SS + n;
            float* c1 = obase + (size_t)(m+8)*SS + n;
            c0[0]=acc[mt*4+nt][0]*SCALE_F; c0[1]=acc[mt*4+nt][1]*SCALE_F;
            c1[0]=acc[mt*4+nt][2]*SCALE_F; c1[1]=acc[mt*4+nt][3]*SCALE_F;
        }
}

// ---------- softmax: warp-per-row, shfl-only (champion) ------------------------------
__global__ void __launch_bounds__(256) softmax_kernel(float* __restrict__ attn)
{
    int lane = threadIdx.x & 31, w = threadIdx.x >> 5;
    size_t row = (size_t)blockIdx.x*8 + w;
    float4* p = (float4*)(attn + row*SS);

    float4 v[8];
#pragma unroll
    for (int i=0;i<8;i++) v[i] = p[lane + i*32];

    float m = -3.0e38f;
#pragma unroll
    for (int i=0;i<8;i++)
        m = fmaxf(m, fmaxf(fmaxf(v[i].x,v[i].y), fmaxf(v[i].z,v[i].w)));
#pragma unroll
    for (int o=16;o;o>>=1) m = fmaxf(m, __shfl_xor_sync(0xffffffffu, m, o));

    float s = 0.f;
#pragma unroll
    for (int i=0;i<8;i++){
        v[i].x = expf(v[i].x - m); v[i].y = expf(v[i].y - m);
        v[i].z = expf(v[i].z - m); v[i].w = expf(v[i].w - m);
        s += (v[i].x + v[i].y) + (v[i].z + v[i].w);
    }
#pragma unroll
    for (int o=16;o;o>>=1) s += __shfl_xor_sync(0xffffffffu, s, o);
    float inv = 1.0f/s;

#pragma unroll
    for (int i=0;i<8;i++){
        float4 e = {v[i].x*inv, v[i].y*inv, v[i].z*inv, v[i].w*inv};
        p[lane + i*32] = e;
    }
}

// ---------- av mma (champion, frozen) -------------------------------------------------
#define AVA 16384
#define AVB 8192
__global__ void __launch_bounds__(256,2) av_mma(
    const float* __restrict__ attn, const __nv_bfloat16* __restrict__ vt,
    __nv_bfloat16* __restrict__ ctxP)
{
    extern __shared__ char smc[];
    int t=threadIdx.x, lane=t&31, wid=t>>5;
    int m0 = blockIdx.x*128, bh = blockIdx.y;
    int b = bh>>4, h = bh&15;
    int wm=(wid>>1)*32, wn=(wid&1)*32;
    uint32_t sb = smem_u32(smc);
    const float* pbase = attn + (size_t)bh*SS*SS + (size_t)m0*SS;

    float acc[8][4];
#pragma unroll
    for (int i=0;i<8;i++)
#pragma unroll
        for (int j=0;j<4;j++) acc[i][j]=0.f;

    for (int ch=0; ch<16; ch++){
        int kc = ch*64;
#pragma unroll
        for (int i=0;i<8;i++){
            int u = t + i*256;
            int r = u>>4, sub = u&15;
            float4 v = *(const float4*)(pbase + (size_t)r*SS + kc + sub*4);
            __nv_bfloat16 h0[4], h1[4];
            float vv[4] = {v.x,v.y,v.z,v.w};
#pragma unroll
            for (int j=0;j<4;j++){
                h0[j] = __float2bfloat16(vv[j]);
                h1[j] = __float2bfloat16(vv[j] - __bfloat162float(h0[j]));
            }
            uint32_t off = (uint32_t)(r*128 + (((sub>>1) ^ (r&7))<<4) + (sub&1)*8);
            *(uint2*)(smc + off)       = *(uint2*)h0;
            *(uint2*)(smc + AVA + off) = *(uint2*)h1;
        }
#pragma unroll
        for (int p=0;p<2;p++){
            const __nv_bfloat16* bs = vt + (size_t)p*VTPL + (size_t)bh*DKK*SS + kc;
            char* db = smc + 2*AVA + p*AVB;
#pragma unroll
            for (int i=0;i<4;i++){
                int u = t + i*256;
                int r = u>>4, sub = u&15;
                uint32_t off = (uint32_t)(r*128 + (((sub>>1) ^ (r&7))<<4) + (sub&1)*8);
                *(uint2*)(db + off) = *(const uint2*)(bs + (size_t)r*SS + sub*4);
            }
        }
        __syncthreads();
#pragma unroll
        for (int ks=0;ks<4;ks++){
            for (int ap=0; ap<2; ap++){
                uint32_t Abase = sb + ap*AVA;
                uint32_t ar[2][4];
#pragma unroll
                for (int mt=0;mt<2;mt++){
                    int r = wm+mt*16+(lane&15);
                    int u16 = ks*2 + (lane>>4);
                    ldsm_x4(ar[mt], Abase + r*128 + ((u16 ^ (r&7))<<4));
                }
                for (int bp=0; bp<2-ap; bp++){
                    uint32_t Bbase = sb + 2*AVA + bp*AVB;
                    uint32_t br[4][2];
#pragma unroll
                    for (int nt=0;nt<4;nt++){
                        int r = wn+nt*8+(lane&7);
                        int u16 = ks*2 + ((lane>>3)&1);
                        ldsm_x2(br[nt], Bbase + r*128 + ((u16 ^ (r&7))<<4));
                    }
#pragma unroll
                    for (int mt=0;mt<2;mt++)
#pragma unroll
                        for (int nt=0;nt<4;nt++)
                            mma16816(acc[mt*4+nt], ar[mt], br[nt]);
                }
            }
        }
        __syncthreads();
    }

    int tr = lane>>2, tc = (lane&3)*2;
#pragma unroll
    for (int mt=0;mt<2;mt++)
#pragma unroll
        for (int nt=0;nt<4;nt++){
            int m = b*SS + m0 + wm + mt*16 + tr;
            int n = h*DKK + wn + nt*8 + tc;
            float* a4 = acc[mt*4+nt];
#pragma unroll
            for (int rr=0;rr<2;rr++){
                int mm = m + rr*8;
                float v0 = a4[rr*2+0], v1 = a4[rr*2+1];
                __nv_bfloat16 p00 = __float2bfloat16(v0);
                __nv_bfloat16 p01 = __float2bfloat16(v1);
                __nv_bfloat16 p10 = __float2bfloat16(v0 - __bfloat162float(p00));
                __nv_bfloat16 p11 = __float2bfloat16(v1 - __bfloat162float(p01));
                *(__nv_bfloat162*)(ctxP + (size_t)mm*DD + n)       = __nv_bfloat162(p00, p01);
                *(__nv_bfloat162*)(ctxP + APL + (size_t)mm*DD + n) = __nv_bfloat162(p10, p11);
            }
        }
}

// ---------------- small c-branch -------------------------------------------------
__global__ void cproj_kernel(const float* __restrict__ c,
    const float* __restrict__ Wcq, const float* __restrict__ bcq,
    const float* __restrict__ Wck, const float* __restrict__ bck,
    const float* __restrict__ Wcv, const float* __restrict__ bcv,
    const float* __restrict__ gqc, const float* __restrict__ beqc,
    const float* __restrict__ gkc, const float* __restrict__ bekc,
    const float* __restrict__ gvc, const float* __restrict__ bevc,
    float* __restrict__ cadd)
{
    int p = blockIdx.x, b = blockIdx.y, t = threadIdx.x;
    const float* W  = (p==0)?Wcq:((p==1)?Wck:Wcv);
    const float* bi = (p==0)?bcq:((p==1)?bck:bcv);
    const float* g  = (p==0)?gqc:((p==1)?gkc:gvc);
    const float* be = (p==0)?beqc:((p==1)?bekc:bevc);
    __shared__ float sc[CFF];
    __shared__ float red[256];
    sc[t] = c[b*CFF + t];
    __syncthreads();
    float y[4];
#pragma unroll
    for (int jj=0;jj<4;jj++){
        int j = jj*256 + t;
        float acc = bi[j];
        for (int i=0;i<CFF;i++) acc += sc[i]*W[(size_t)i*DD + j];
        y[jj]=acc;
    }
    float s=(y[0]+y[1])+(y[2]+y[3]);
    red[t]=s; __syncthreads();
    for (int st=128;st>0;st>>=1){ if(t<st) red[t]+=red[t+st]; __syncthreads(); }
    float mu = red[0]*(1.0f/DD);
    __syncthreads();
    float vv=0.f;
#pragma unroll
    for (int jj=0;jj<4;jj++){ float d0=y[jj]-mu; vv += d0*d0; }
    red[t]=vv; __syncthreads();
    for (int st=128;st>0;st>>=1){ if(t<st) red[t]+=red[t+st]; __syncthreads(); }
    float rs = 1.0f/sqrtf(red[0]*(1.0f/DD) + 1e-5f);
#pragma unroll
    for (int jj=0;jj<4;jj++){
        int j = jj*256 + t;
        cadd[(size_t)(p*BB + b)*DD + j] = (y[jj]-mu)*rs*g[j] + be[j];
    }
}

// ---------- merged LN: z=0 -> v (fp32 out), z=1 -> q planes, z=2 -> k planes --------
__global__ void lnfused_kernel(
    float* __restrict__ vbuf, const float* __restrict__ qbuf, const float* __restrict__ kbuf,
    const float* __restrict__ g_v, const float* __restrict__ be_v,
    const float* __restrict__ g_q, const float* __restrict__ be_q,
    const float* __restrict__ g_k, const float* __restrict__ be_k,
    const float* __restrict__ cadd,
    __nv_bfloat16* __restrict__ qP, __nv_bfloat16* __restrict__ kP)
{
    __shared__ float red[256];
    int t = threadIdx.x, r = blockIdx.x, z = blockIdx.y;
    const float* buf = (z==0)?vbuf:((z==1)?qbuf:kbuf);
    const float* g   = (z==0)?g_v:((z==1)?g_q:g_k);
    const float* be  = (z==0)?be_v:((z==1)?be_q:be_k);
    const float* ca  = cadd + (size_t)(((z==0)?2:(z-1))*BB + (r>>10))*DD;

    const float4* row = (const float4*)(buf + (size_t)r*DD);
    float4 v = row[t];
    red[t]=(v.x+v.y)+(v.z+v.w); __syncthreads();
    for (int st=128;st>0;st>>=1){ if(t<st) red[t]+=red[t+st]; __syncthreads(); }
    float mu = red[0]*(1.0f/DD);
    __syncthreads();
    float dx=v.x-mu, dy=v.y-mu, dz=v.z-mu, dw=v.w-mu;
    red[t]=(dx*dx+dy*dy)+(dz*dz+dw*dw); __syncthreads();
    for (int st=128;st>0;st>>=1){ if(t<st) red[t]+=red[t+st]; __syncthreads(); }
    float rs = 1.0f/sqrtf(red[0]*(1.0f/DD) + 1e-5f);
    float4 gg=((const float4*)g)[t], bb=((const float4*)be)[t];
    float4 cc=((const float4*)ca)[t];
    float o[4] = {dx*rs*gg.x+bb.x+cc.x, dy*rs*gg.y+bb.y+cc.y,
                  dz*rs*gg.z+bb.z+cc.z, dw*rs*gg.w+bb.w+cc.w};
    if (z==0){
        float4 ov = {o[0],o[1],o[2],o[3]};
        ((float4*)(vbuf + (size_t)r*DD))[t] = ov;
    } else {
        __nv_bfloat16* P = (z==1)?qP:kP;
        __nv_bfloat16 h[3][4];
#pragma unroll
        for (int j=0;j<4;j++) split3(o[j], h[0][j], h[1][j], h[2][j]);
        size_t base = (size_t)r*DD + t*4;
#pragma unroll
        for (int p=0;p<3;p++)
            *(uint2*)(P + p*APL + base) = *(uint2*)h[p];
    }
}

// ------------------------------- launch ---------------------------------------------
extern "C" void kernel_launch(void* const* d_in, const int* in_sizes, int n_in,
                              void* d_out, int out_size)
{
    const float* Q    = (const float*)d_in[0];
    const float* c    = (const float*)d_in[1];
    const float* Wq   = (const float*)d_in[2];
    const float* bq   = (const float*)d_in[3];
    const float* Wk   = (const float*)d_in[4];
    const float* bk   = (const float*)d_in[5];
    const float* Wv   = (const float*)d_in[6];
    const float* bv   = (const float*)d_in[7];
    const float* Wcq  = (const float*)d_in[8];
    const float* bcq  = (const float*)d_in[9];
    const float* Wck  = (const float*)d_in[10];
    const float* bck  = (const float*)d_in[11];
    const float* Wcv  = (const float*)d_in[12];
    const float* bcv  = (const float*)d_in[13];
    const float* g_q  = (const float*)d_in[14];
    const float* be_q = (const float*)d_in[15];
    const float* g_qc = (const float*)d_in[16];
    const float* be_qc= (const float*)d_in[17];
    const float* g_k  = (const float*)d_in[18];
    const float* be_k = (const float*)d_in[19];
    const float* g_kc = (const float*)d_in[20];
    const float* be_kc= (const float*)d_in[21];
    const float* g_v  = (const float*)d_in[22];
    const float* be_v = (const float*)d_in[23];
    const float* g_vc = (const float*)d_in[24];
    const float* be_vc= (const float*)d_in[25];
    const float* Wo   = (const float*)d_in[26];
    const float* bo   = (const float*)d_in[27];

    float* out  = (float*)d_out;
    float* attn = out + OUT_ELEMS;

    float *qb,*kb,*vbuf,*cadd;
    __nv_bfloat16 *apl,*kpl,*wpl,*vtp;
    cudaGetSymbolAddress((void**)&qb,   d_qbuf);
    cudaGetSymbolAddress((void**)&kb,   d_kbuf);
    cudaGetSymbolAddress((void**)&vbuf, d_vbuf);
    cudaGetSymbolAddress((void**)&cadd, d_caddbuf);
    cudaGetSymbolAddress((void**)&apl,  d_aplanes);
    cudaGetSymbolAddress((void**)&kpl,  d_kplanes);
    cudaGetSymbolAddress((void**)&wpl,  d_wplanes);
    cudaGetSymbolAddress((void**)&vtp,  d_vtpl);

    cudaFuncSetAttribute(gemm_mma_qkv, cudaFuncAttributeMaxDynamicSharedMemorySize, GEMM_SMEM_MAX);
    cudaFuncSetAttribute(gemm_mma,     cudaFuncAttributeMaxDynamicSharedMemorySize, GEMM_SMEM_MAX);
    cudaFuncSetAttribute(qk_mma,       cudaFuncAttributeMaxDynamicSharedMemorySize, 6*QKPL);
    cudaFuncSetAttribute(av_mma,       cudaFuncAttributeMaxDynamicSharedMemorySize, 2*AVA+2*AVB);

    cproj_kernel<<<dim3(3,BB),256>>>(c, Wcq,bcq, Wck,bck, Wcv,bcv,
                                     g_qc,be_qc, g_kc,be_kc, g_vc,be_vc, cadd);

    splitWT_kernel<<<dim3(32,32,4),256>>>(Wq, Wk, Wv, Wo, wpl);
    splitA_kernel<<<MT,256>>>(Q, apl);

    gemm_mma_qkv<<<dim3(DD/128, MT/128, 3),256,GEMM_SMEM_MAX>>>(
        apl, wpl, bq, bk, bv, qb, kb, vbuf);

    // merged LN: v (fp32, in-place) + q/k (3-plane split), one launch
    lnfused_kernel<<<dim3(MT,3),256>>>(vbuf, qb, kb,
        g_v, be_v, g_q, be_q, g_k, be_k, cadd, apl, kpl);

    vtrans_kernel<<<dim3(2,32,BB*HH),256>>>(vbuf, vtp);

    qk_mma<<<dim3(SS/128, SS/128, BB*HH),256,6*QKPL>>>(apl, kpl, attn);
    softmax_kernel<<<BB*HH*SS/8,256>>>(attn);
    av_mma<<<dim3(SS/128, BB*HH),256,2*AVA+2*AVB>>>(attn, vtp, apl);

    gemm_mma<<<dim3(DD/128, MT/128),256,4*PLSZ>>>(apl, wpl + 3*3*WPL, bo, out, 3);
}

// round 17
// speedup vs baseline: 1.0152x; 1.0152x over previous
#include <cuda_runtime.h>
#include <cuda_bf16.h>
#include <math.h>
#include <stdint.h>

#define BB   8
#define SS   1024
#define DD   1024
#define HH   16
#define DKK  64
#define CFF  256
#define MT   (BB*SS)
#define OUT_ELEMS  (MT*DD)
#define SCALE_F 512.0f

__device__ float d_qbuf[MT*DD];
__device__ float d_kbuf[MT*DD];
__device__ float d_vbuf[MT*DD];
__device__ float d_caddbuf[3*BB*DD];
__device__ __nv_bfloat16 d_aplanes[(size_t)3*MT*DD];
__device__ __nv_bfloat16 d_kplanes[(size_t)3*MT*DD];
__device__ __nv_bfloat16 d_wplanes[(size_t)4*3*DD*DD];
__device__ __nv_bfloat16 d_vtpl[(size_t)2*MT*DD];     // V planes, natural row-major

#define APL ((size_t)MT*DD)
#define WPL ((size_t)DD*DD)
#define VTPL ((size_t)MT*DD)

// ---------------- helpers -------------------------------------------------------
__device__ __forceinline__ uint32_t smem_u32(const void* p){
    uint32_t a; asm("{.reg .u64 t; cvta.to.shared.u64 t, %1; cvt.u32.u64 %0, t;}":"=r"(a):"l"(p)); return a;
}
__device__ __forceinline__ void ldsm_x4(uint32_t* r, uint32_t addr){
    asm volatile("ldmatrix.sync.aligned.m8n8.x4.shared.b16 {%0,%1,%2,%3}, [%4];"
        : "=r"(r[0]),"=r"(r[1]),"=r"(r[2]),"=r"(r[3]) : "r"(addr));
}
__device__ __forceinline__ void ldsm_x2(uint32_t* r, uint32_t addr){
    asm volatile("ldmatrix.sync.aligned.m8n8.x2.shared.b16 {%0,%1}, [%2];"
        : "=r"(r[0]),"=r"(r[1]) : "r"(addr));
}
__device__ __forceinline__ void ldsm_x2_trans(uint32_t* r, uint32_t addr){
    asm volatile("ldmatrix.sync.aligned.m8n8.x2.trans.shared.b16 {%0,%1}, [%2];"
        : "=r"(r[0]),"=r"(r[1]) : "r"(addr));
}
__device__ __forceinline__ void mma16816(float* d, const uint32_t* a, const uint32_t* b){
    asm volatile("mma.sync.aligned.m16n8k16.row.col.f32.bf16.bf16.f32 "
        "{%0,%1,%2,%3}, {%4,%5,%6,%7}, {%8,%9}, {%0,%1,%2,%3};"
        : "+f"(d[0]),"+f"(d[1]),"+f"(d[2]),"+f"(d[3])
        : "r"(a[0]),"r"(a[1]),"r"(a[2]),"r"(a[3]), "r"(b[0]),"r"(b[1]));
}
__device__ __forceinline__ void split3(float a, __nv_bfloat16& h0, __nv_bfloat16& h1, __nv_bfloat16& h2){
    h0 = __float2bfloat16(a);
    float r = a - __bfloat162float(h0);
    h1 = __float2bfloat16(r);
    h2 = __float2bfloat16(r - __bfloat162float(h1));
}

__global__ void splitA_kernel(const float* __restrict__ X, __nv_bfloat16* __restrict__ P){
    size_t base = (size_t)blockIdx.x*DD;
    int t = threadIdx.x;
    float4 v = ((const float4*)(X+base))[t];
    __nv_bfloat16 a[3], b[3], c[3], d[3];
    split3(v.x,a[0],a[1],a[2]); split3(v.y,b[0],b[1],b[2]);
    split3(v.z,c[0],c[1],c[2]); split3(v.w,d[0],d[1],d[2]);
#pragma unroll
    for (int p=0;p<3;p++){
        __nv_bfloat162* dst = (__nv_bfloat162*)(P + p*APL + base + t*4);
        dst[0] = __nv_bfloat162(a[p], b[p]);
        dst[1] = __nv_bfloat162(c[p], d[p]);
    }
}

__global__ void splitWT_kernel(const float* __restrict__ W0, const float* __restrict__ W1,
                               const float* __restrict__ W2, const float* __restrict__ W3,
                               __nv_bfloat16* __restrict__ Pall){
    __shared__ float tile[32][33];
    int z = blockIdx.z;
    const float* W = (z==0)?W0:((z==1)?W1:((z==2)?W2:W3));
    __nv_bfloat16* P = Pall + (size_t)z*3*WPL;
    int n0 = blockIdx.x*32, k0 = blockIdx.y*32;
    int tx = threadIdx.x&31, ty = threadIdx.x>>5;
#pragma unroll
    for (int i=0;i<32;i+=8)
        tile[ty+i][tx] = W[(size_t)(k0+ty+i)*DD + n0+tx];
    __syncthreads();
#pragma unroll
    for (int i=0;i<32;i+=8){
        float a = tile[tx][ty+i];
        __nv_bfloat16 h0,h1,h2; split3(a,h0,h1,h2);
        size_t o = (size_t)(n0+ty+i)*DD + k0+tx;
        P[0*WPL+o]=h0; P[1*WPL+o]=h1; P[2*WPL+o]=h2;
    }
}

// ---------- split-bf16 mma.sync GEMM (champion core, z-merged q/k/v) ----------------
#define STRB  144
#define PLSZ  (128*STRB)
#define GEMM_SMEM_MAX (6*PLSZ)

__device__ __forceinline__ void gemm_body(
    const __nv_bfloat16* __restrict__ Apl, const __nv_bfloat16* __restrict__ Bpl,
    const float* __restrict__ bias, float* __restrict__ C, int pc, char* smc)
{
    int t=threadIdx.x, lane=t&31, wid=t>>5;
    int m0=blockIdx.y*128, n0=blockIdx.x*128;
    int wm=(wid>>2)*64, wn=(wid&3)*32;
    uint32_t sb = smem_u32(smc);

    float acc[16][4];
#pragma unroll
    for (int i=0;i<16;i++)
#pragma unroll
        for (int j=0;j<4;j++) acc[i][j]=0.f;

    for (int ch=0; ch<16; ch++){
        int kc = ch*64;
        for (int p=0;p<pc;p++){
            const __nv_bfloat16* As  = Apl + (size_t)p*APL + (size_t)m0*DD + kc;
            const __nv_bfloat16* Bs2 = Bpl + (size_t)p*WPL + (size_t)n0*DD + kc;
            char* da = smc + p*PLSZ;
            char* db = smc + (pc+p)*PLSZ;
#pragma unroll
            for (int i=0;i<8;i++){
                int idx=t+i*256, r=idx>>4, c4=(idx&15)*4;
                uint2 va = *(const uint2*)(As  + (size_t)r*DD + c4);
                *(uint2*)(da + r*STRB + c4*2) = va;
                uint2 vb = *(const uint2*)(Bs2 + (size_t)r*DD + c4);
                *(uint2*)(db + r*STRB + c4*2) = vb;
            }
        }
        __syncthreads();
#pragma unroll
        for (int ks=0;ks<4;ks++){
            for (int ap=0; ap<pc; ap++){
                uint32_t Abase = sb + ap*PLSZ;
                uint32_t ar[4][4];
#pragma unroll
                for (int mt=0;mt<4;mt++)
                    ldsm_x4(ar[mt], Abase + (wm+mt*16+(lane&15))*STRB + ks*32 + (lane>>4)*16);
                for (int bp=0; bp<pc-ap; bp++){
                    uint32_t Bbase = sb + (pc+bp)*PLSZ;
                    uint32_t br[4][2];
#pragma unroll
                    for (int nt=0;nt<4;nt++)
                        ldsm_x2(br[nt], Bbase + (wn+nt*8+(lane&7))*STRB + ks*32 + ((lane>>3)&1)*16);
#pragma unroll
                    for (int mt=0;mt<4;mt++)
#pragma unroll
                        for (int nt=0;nt<4;nt++)
                            mma16816(acc[mt*4+nt], ar[mt], br[nt]);
                }
            }
        }
        __syncthreads();
    }

    int tr = lane>>2, tc = (lane&3)*2;
#pragma unroll
    for (int mt=0;mt<4;mt++)
#pragma unroll
        for (int nt=0;nt<4;nt++){
            int m = m0+wm+mt*16+tr, n = n0+wn+nt*8+tc;
            float b0 = bias[n], b1 = bias[n+1];
            float* c0 = C + (size_t)m*DD + n;
            float* c1 = C + (size_t)(m+8)*DD + n;
            c0[0]=acc[mt*4+nt][0]+b0; c0[1]=acc[mt*4+nt][1]+b1;
            c1[0]=acc[mt*4+nt][2]+b0; c1[1]=acc[mt*4+nt][3]+b1;
        }
}

__global__ void __launch_bounds__(256,2) gemm_mma_qkv(
    const __nv_bfloat16* __restrict__ Apl, const __nv_bfloat16* __restrict__ Wall,
    const float* __restrict__ bq, const float* __restrict__ bk, const float* __restrict__ bv,
    float* __restrict__ qb, float* __restrict__ kb, float* __restrict__ vb)
{
    extern __shared__ char smc[];
    int z = blockIdx.z;
    const __nv_bfloat16* Bpl = Wall + (size_t)z*3*WPL;
    const float* bias = (z==0)?bq:((z==1)?bk:bv);
    float* C = (z==0)?qb:((z==1)?kb:vb);
    int pc = (z==2)?2:3;
    gemm_body(Apl, Bpl, bias, C, pc, smc);
}

__global__ void __launch_bounds__(256,2) gemm_mma(
    const __nv_bfloat16* __restrict__ Apl, const __nv_bfloat16* __restrict__ Bpl,
    const float* __restrict__ bias, float* __restrict__ C, int npairs)
{
    extern __shared__ char smc[];
    gemm_body(Apl, Bpl, bias, C, (npairs==6)?3:2, smc);
}

// ---------- qk mma (champion, frozen) ------------------------------------------------
#define QKPL 16384
__global__ void __launch_bounds__(256,2) qk_mma(
    const __nv_bfloat16* __restrict__ qpl, const __nv_bfloat16* __restrict__ kpl,
    float* __restrict__ attn)
{
    extern __shared__ char smc[];
    int t=threadIdx.x, lane=t&31, wid=t>>5;
    int bh = blockIdx.z, b = bh>>4, h = bh&15;
    int m0 = blockIdx.y*128, n0 = blockIdx.x*128;
    int wm=(wid>>2)*64, wn=(wid&3)*32;
    uint32_t sb = smem_u32(smc);

#pragma unroll
    for (int p=0;p<3;p++){
        const __nv_bfloat16* qs = qpl + (size_t)p*APL + (size_t)(b*SS+m0)*DD + h*DKK;
        const __nv_bfloat16* ks2= kpl + (size_t)p*APL + (size_t)(b*SS+n0)*DD + h*DKK;
        char* da = smc + p*QKPL;
        char* db = smc + (3+p)*QKPL;
#pragma unroll
        for (int i=0;i<8;i++){
            int u = t + i*256;
            int r = u>>4, sub = u&15;
            uint32_t off = (uint32_t)(r*128 + (((sub>>1) ^ (r&7))<<4) + (sub&1)*8);
            *(uint2*)(da + off) = *(const uint2*)(qs + (size_t)r*DD + sub*4);
            *(uint2*)(db + off) = *(const uint2*)(ks2 + (size_t)r*DD + sub*4);
        }
    }
    __syncthreads();

    float acc[16][4];
#pragma unroll
    for (int i=0;i<16;i++)
#pragma unroll
        for (int j=0;j<4;j++) acc[i][j]=0.f;

#pragma unroll
    for (int ks=0;ks<4;ks++){
        for (int ap=0; ap<3; ap++){
            uint32_t Abase = sb + ap*QKPL;
            uint32_t ar[4][4];
#pragma unroll
            for (int mt=0;mt<4;mt++){
                int r = wm+mt*16+(lane&15);
                int u16 = ks*2 + (lane>>4);
                ldsm_x4(ar[mt], Abase + r*128 + ((u16 ^ (r&7))<<4));
            }
            for (int bp=0; bp<3-ap; bp++){
                uint32_t Bbase = sb + (3+bp)*QKPL;
                uint32_t br[4][2];
#pragma unroll
                for (int nt=0;nt<4;nt++){
                    int r = wn+nt*8+(lane&7);
                    int u16 = ks*2 + ((lane>>3)&1);
                    ldsm_x2(br[nt], Bbase + r*128 + ((u16 ^ (r&7))<<4));
                }
#pragma unroll
                for (int mt=0;mt<4;mt++)
#pragma unroll
                    for (int nt=0;nt<4;nt++)
                        mma16816(acc[mt*4+nt], ar[mt], br[nt]);
            }
        }
    }

    float* obase = attn + (size_t)bh*SS*SS;
    int tr = lane>>2, tc = (lane&3)*2;
#pragma unroll
    for (int mt=0;mt<4;mt++)
#pragma unroll
        for (int nt=0;nt<4;nt++){
            int m = m0+wm+mt*16+tr, n = n0+wn+nt*8+tc;
            float* c0 = obase + (size_t)m*SS + n;
            float* c1 = obase + (size_t)(m+8)*SS + n;
            c0[0]=acc[mt*4+nt][0]*SCALE_F; c0[1]=acc[mt*4+nt][1]*SCALE_F;
            c1[0]=acc[mt*4+nt][2]*SCALE_F; c1[1]=acc[mt*4+nt][3]*SCALE_F;
        }
}

// ---------- softmax: warp-per-row, shfl-only (champion) ------------------------------
__global__ void __launch_bounds__(256) softmax_kernel(float* __restrict__ attn)
{
    int lane = threadIdx.x & 31, w = threadIdx.x >> 5;
    size_t row = (size_t)blockIdx.x*8 + w;
    float4* p = (float4*)(attn + row*SS);

    float4 v[8];
#pragma unroll
    for (int i=0;i<8;i++) v[i] = p[lane + i*32];

    float m = -3.0e38f;
#pragma unroll
    for (int i=0;i<8;i++)
        m = fmaxf(m, fmaxf(fmaxf(v[i].x,v[i].y), fmaxf(v[i].z,v[i].w)));
#pragma unroll
    for (int o=16;o;o>>=1) m = fmaxf(m, __shfl_xor_sync(0xffffffffu, m, o));

    float s = 0.f;
#pragma unroll
    for (int i=0;i<8;i++){
        v[i].x = expf(v[i].x - m); v[i].y = expf(v[i].y - m);
        v[i].z = expf(v[i].z - m); v[i].w = expf(v[i].w - m);
        s += (v[i].x + v[i].y) + (v[i].z + v[i].w);
    }
#pragma unroll
    for (int o=16;o;o>>=1) s += __shfl_xor_sync(0xffffffffu, s, o);
    float inv = 1.0f/s;

#pragma unroll
    for (int i=0;i<8;i++){
        float4 e = {v[i].x*inv, v[i].y*inv, v[i].z*inv, v[i].w*inv};
        p[lane + i*32] = e;
    }
}

// ---------- av mma: V natural-layout planes + ldmatrix.trans B-load -----------------
#define AVA 16384
#define AVB 8192
__global__ void __launch_bounds__(256,2) av_mma(
    const float* __restrict__ attn, const __nv_bfloat16* __restrict__ vt,
    __nv_bfloat16* __restrict__ ctxP)
{
    extern __shared__ char smc[];
    int t=threadIdx.x, lane=t&31, wid=t>>5;
    int m0 = blockIdx.x*128, bh = blockIdx.y;
    int b = bh>>4, h = bh&15;
    int wm=(wid>>1)*32, wn=(wid&1)*32;
    uint32_t sb = smem_u32(smc);
    const float* pbase = attn + (size_t)bh*SS*SS + (size_t)m0*SS;

    float acc[8][4];
#pragma unroll
    for (int i=0;i<8;i++)
#pragma unroll
        for (int j=0;j<4;j++) acc[i][j]=0.f;

    for (int ch=0; ch<16; ch++){
        int kc = ch*64;
        // P fp32 -> 2 bf16 planes in smem (swizzled 128B rows)
#pragma unroll
        for (int i=0;i<8;i++){
            int u = t + i*256;
            int r = u>>4, sub = u&15;
            float4 v = *(const float4*)(pbase + (size_t)r*SS + kc + sub*4);
            __nv_bfloat16 h0[4], h1[4];
            float vv[4] = {v.x,v.y,v.z,v.w};
#pragma unroll
            for (int j=0;j<4;j++){
                h0[j] = __float2bfloat16(vv[j]);
                h1[j] = __float2bfloat16(vv[j] - __bfloat162float(h0[j]));
            }
            uint32_t off = (uint32_t)(r*128 + (((sub>>1) ^ (r&7))<<4) + (sub&1)*8);
            *(uint2*)(smc + off)       = *(uint2*)h0;
            *(uint2*)(smc + AVA + off) = *(uint2*)h1;
        }
        // V planes: natural layout rows [s][d], 64 rows x 64 cols = 128B rows
#pragma unroll
        for (int p=0;p<2;p++){
            const __nv_bfloat16* bs = vt + (size_t)p*VTPL + (size_t)(b*SS + kc)*DD + h*DKK;
            char* db = smc + 2*AVA + p*AVB;
#pragma unroll
            for (int i=0;i<4;i++){
                int u = t + i*256;
                int r = u>>4, sub = u&15;
                uint32_t off = (uint32_t)(r*128 + (((sub>>1) ^ (r&7))<<4) + (sub&1)*8);
                *(uint2*)(db + off) = *(const uint2*)(bs + (size_t)r*DD + sub*4);
            }
        }
        __syncthreads();
#pragma unroll
        for (int ks=0;ks<4;ks++){
            for (int ap=0; ap<2; ap++){
                uint32_t Abase = sb + ap*AVA;
                uint32_t ar[2][4];
#pragma unroll
                for (int mt=0;mt<2;mt++){
                    int r = wm+mt*16+(lane&15);
                    int u16 = ks*2 + (lane>>4);
                    ldsm_x4(ar[mt], Abase + r*128 + ((u16 ^ (r&7))<<4));
                }
                for (int bp=0; bp<2-ap; bp++){
                    uint32_t Bbase = sb + 2*AVA + bp*AVB;
                    uint32_t br[4][2];
#pragma unroll
                    for (int nt=0;nt<4;nt++){
                        int r = ks*16 + (lane&15);           // k rows of this tile
                        int u16 = (wn + nt*8) >> 3;          // 16B unit of n-col start
                        ldsm_x2_trans(br[nt], Bbase + r*128 + ((u16 ^ (r&7))<<4));
                    }
#pragma unroll
                    for (int mt=0;mt<2;mt++)
#pragma unroll
                        for (int nt=0;nt<4;nt++)
                            mma16816(acc[mt*4+nt], ar[mt], br[nt]);
                }
            }
        }
        __syncthreads();
    }

    int tr = lane>>2, tc = (lane&3)*2;
#pragma unroll
    for (int mt=0;mt<2;mt++)
#pragma unroll
        for (int nt=0;nt<4;nt++){
            int m = b*SS + m0 + wm + mt*16 + tr;
            int n = h*DKK + wn + nt*8 + tc;
            float* a4 = acc[mt*4+nt];
#pragma unroll
            for (int rr=0;rr<2;rr++){
                int mm = m + rr*8;
                float v0 = a4[rr*2+0], v1 = a4[rr*2+1];
                __nv_bfloat16 p00 = __float2bfloat16(v0);
                __nv_bfloat16 p01 = __float2bfloat16(v1);
                __nv_bfloat16 p10 = __float2bfloat16(v0 - __bfloat162float(p00));
                __nv_bfloat16 p11 = __float2bfloat16(v1 - __bfloat162float(p01));
                *(__nv_bfloat162*)(ctxP + (size_t)mm*DD + n)       = __nv_bfloat162(p00, p01);
                *(__nv_bfloat162*)(ctxP + APL + (size_t)mm*DD + n) = __nv_bfloat162(p10, p11);
            }
        }
}

// ---------------- small c-branch -------------------------------------------------
__global__ void cproj_kernel(const float* __restrict__ c,
    const float* __restrict__ Wcq, const float* __restrict__ bcq,
    const float* __restrict__ Wck, const float* __restrict__ bck,
    const float* __restrict__ Wcv, const float* __restrict__ bcv,
    const float* __restrict__ gqc, const float* __restrict__ beqc,
    const float* __restrict__ gkc, const float* __restrict__ bekc,
    const float* __restrict__ gvc, const float* __restrict__ bevc,
    float* __restrict__ cadd)
{
    int p = blockIdx.x, b = blockIdx.y, t = threadIdx.x;
    const float* W  = (p==0)?Wcq:((p==1)?Wck:Wcv);
    const float* bi = (p==0)?bcq:((p==1)?bck:bcv);
    const float* g  = (p==0)?gqc:((p==1)?gkc:gvc);
    const float* be = (p==0)?beqc:((p==1)?bekc:bevc);
    __shared__ float sc[CFF];
    __shared__ float red[256];
    sc[t] = c[b*CFF + t];
    __syncthreads();
    float y[4];
#pragma unroll
    for (int jj=0;jj<4;jj++){
        int j = jj*256 + t;
        float acc = bi[j];
        for (int i=0;i<CFF;i++) acc += sc[i]*W[(size_t)i*DD + j];
        y[jj]=acc;
    }
    float s=(y[0]+y[1])+(y[2]+y[3]);
    red[t]=s; __syncthreads();
    for (int st=128;st>0;st>>=1){ if(t<st) red[t]+=red[t+st]; __syncthreads(); }
    float mu = red[0]*(1.0f/DD);
    __syncthreads();
    float vv=0.f;
#pragma unroll
    for (int jj=0;jj<4;jj++){ float d0=y[jj]-mu; vv += d0*d0; }
    red[t]=vv; __syncthreads();
    for (int st=128;st>0;st>>=1){ if(t<st) red[t]+=red[t+st]; __syncthreads(); }
    float rs = 1.0f/sqrtf(red[0]*(1.0f/DD) + 1e-5f);
#pragma unroll
    for (int jj=0;jj<4;jj++){
        int j = jj*256 + t;
        cadd[(size_t)(p*BB + b)*DD + j] = (y[jj]-mu)*rs*g[j] + be[j];
    }
}

// ---------- merged LN: z=0 -> v 2-plane bf16, z=1 -> q planes, z=2 -> k planes ------
__global__ void lnfused_kernel(
    const float* __restrict__ vbuf, const float* __restrict__ qbuf, const float* __restrict__ kbuf,
    const float* __restrict__ g_v, const float* __restrict__ be_v,
    const float* __restrict__ g_q, const float* __restrict__ be_q,
    const float* __restrict__ g_k, const float* __restrict__ be_k,
    const float* __restrict__ cadd,
    __nv_bfloat16* __restrict__ qP, __nv_bfloat16* __restrict__ kP,
    __nv_bfloat16* __restrict__ vP)
{
    __shared__ float red[256];
    int t = threadIdx.x, r = blockIdx.x, z = blockIdx.y;
    const float* buf = (z==0)?vbuf:((z==1)?qbuf:kbuf);
    const float* g   = (z==0)?g_v:((z==1)?g_q:g_k);
    const float* be  = (z==0)?be_v:((z==1)?be_q:be_k);
    const float* ca  = cadd + (size_t)(((z==0)?2:(z-1))*BB + (r>>10))*DD;

    const float4* row = (const float4*)(buf + (size_t)r*DD);
    float4 v = row[t];
    red[t]=(v.x+v.y)+(v.z+v.w); __syncthreads();
    for (int st=128;st>0;st>>=1){ if(t<st) red[t]+=red[t+st]; __syncthreads(); }
    float mu = red[0]*(1.0f/DD);
    __syncthreads();
    float dx=v.x-mu, dy=v.y-mu, dz=v.z-mu, dw=v.w-mu;
    red[t]=(dx*dx+dy*dy)+(dz*dz+dw*dw); __syncthreads();
    for (int st=128;st>0;st>>=1){ if(t<st) red[t]+=red[t+st]; __syncthreads(); }
    float rs = 1.0f/sqrtf(red[0]*(1.0f/DD) + 1e-5f);
    float4 gg=((const float4*)g)[t], bb=((const float4*)be)[t];
    float4 cc=((const float4*)ca)[t];
    float o[4] = {dx*rs*gg.x+bb.x+cc.x, dy*rs*gg.y+bb.y+cc.y,
                  dz*rs*gg.z+bb.z+cc.z, dw*rs*gg.w+bb.w+cc.w};
    size_t base = (size_t)r*DD + t*4;
    if (z==0){
        __nv_bfloat16 h0[4], h1[4];
#pragma unroll
        for (int j=0;j<4;j++){
            h0[j] = __float2bfloat16(o[j]);
            h1[j] = __float2bfloat16(o[j] - __bfloat162float(h0[j]));
        }
        *(uint2*)(vP + base)        = *(uint2*)h0;
        *(uint2*)(vP + VTPL + base) = *(uint2*)h1;
    } else {
        __nv_bfloat16* P = (z==1)?qP:kP;
        __nv_bfloat16 h[3][4];
#pragma unroll
        for (int j=0;j<4;j++) split3(o[j], h[0][j], h[1][j], h[2][j]);
#pragma unroll
        for (int p=0;p<3;p++)
            *(uint2*)(P + p*APL + base) = *(uint2*)h[p];
    }
}

// ------------------------------- launch ---------------------------------------------
extern "C" void kernel_launch(void* const* d_in, const int* in_sizes, int n_in,
                              void* d_out, int out_size)
{
    const float* Q    = (const float*)d_in[0];
    const float* c    = (const float*)d_in[1];
    const float* Wq   = (const float*)d_in[2];
    const float* bq   = (const float*)d_in[3];
    const float* Wk   = (const float*)d_in[4];
    const float* bk   = (const float*)d_in[5];
    const float* Wv   = (const float*)d_in[6];
    const float* bv   = (const float*)d_in[7];
    const float* Wcq  = (const float*)d_in[8];
    const float* bcq  = (const float*)d_in[9];
    const float* Wck  = (const float*)d_in[10];
    const float* bck  = (const float*)d_in[11];
    const float* Wcv  = (const float*)d_in[12];
    const float* bcv  = (const float*)d_in[13];
    const float* g_q  = (const float*)d_in[14];
    const float* be_q = (const float*)d_in[15];
    const float* g_qc = (const float*)d_in[16];
    const float* be_qc= (const float*)d_in[17];
    const float* g_k  = (const float*)d_in[18];
    const float* be_k = (const float*)d_in[19];
    const float* g_kc = (const float*)d_in[20];
    const float* be_kc= (const float*)d_in[21];
    const float* g_v  = (const float*)d_in[22];
    const float* be_v = (const float*)d_in[23];
    const float* g_vc = (const float*)d_in[24];
    const float* be_vc= (const float*)d_in[25];
    const float* Wo   = (const float*)d_in[26];
    const float* bo   = (const float*)d_in[27];

    float* out  = (float*)d_out;
    float* attn = out + OUT_ELEMS;

    float *qb,*kb,*vbuf,*cadd;
    __nv_bfloat16 *apl,*kpl,*wpl,*vtp;
    cudaGetSymbolAddress((void**)&qb,   d_qbuf);
    cudaGetSymbolAddress((void**)&kb,   d_kbuf);
    cudaGetSymbolAddress((void**)&vbuf, d_vbuf);
    cudaGetSymbolAddress((void**)&cadd, d_caddbuf);
    cudaGetSymbolAddress((void**)&apl,  d_aplanes);
    cudaGetSymbolAddress((void**)&kpl,  d_kplanes);
    cudaGetSymbolAddress((void**)&wpl,  d_wplanes);
    cudaGetSymbolAddress((void**)&vtp,  d_vtpl);

    cudaFuncSetAttribute(gemm_mma_qkv, cudaFuncAttributeMaxDynamicSharedMemorySize, GEMM_SMEM_MAX);
    cudaFuncSetAttribute(gemm_mma,     cudaFuncAttributeMaxDynamicSharedMemorySize, GEMM_SMEM_MAX);
    cudaFuncSetAttribute(qk_mma,       cudaFuncAttributeMaxDynamicSharedMemorySize, 6*QKPL);
    cudaFuncSetAttribute(av_mma,       cudaFuncAttributeMaxDynamicSharedMemorySize, 2*AVA+2*AVB);

    cproj_kernel<<<dim3(3,BB),256>>>(c, Wcq,bcq, Wck,bck, Wcv,bcv,
                                     g_qc,be_qc, g_kc,be_kc, g_vc,be_vc, cadd);

    splitWT_kernel<<<dim3(32,32,4),256>>>(Wq, Wk, Wv, Wo, wpl);
    splitA_kernel<<<MT,256>>>(Q, apl);

    gemm_mma_qkv<<<dim3(DD/128, MT/128, 3),256,GEMM_SMEM_MAX>>>(
        apl, wpl, bq, bk, bv, qb, kb, vbuf);

    // merged LN: v -> 2 bf16 planes (natural layout), q/k -> 3-plane splits
    lnfused_kernel<<<dim3(MT,3),256>>>(vbuf, qb, kb,
        g_v, be_v, g_q, be_q, g_k, be_k, cadd, apl, kpl, vtp);

    qk_mma<<<dim3(SS/128, SS/128, BB*HH),256,6*QKPL>>>(apl, kpl, attn);
    softmax_kernel<<<BB*HH*SS/8,256>>>(attn);
    av_mma<<<dim3(SS/128, BB*HH),256,2*AVA+2*AVB>>>(attn, vtp, apl);

    gemm_mma<<<dim3(DD/128, MT/128),256,4*PLSZ>>>(apl, wpl + 3*3*WPL, bo, out, 3);
}